// round 4
// baseline (speedup 1.0000x reference)
#include <cuda_runtime.h>
#include <cstdint>

// Sinkhorn on B x 64 x 64 matrices, scaling-vector form, TWO warps per matrix.
// Each warp owns 32 rows; K frozen in regs (row-packed f32x2); col pass does an
// in-warp butterfly + per-tj smem exchange (double buffered) + named barrier.

typedef unsigned long long u64;
#define FULLMASK 0xffffffffu

__device__ __forceinline__ u64 pk2(float lo, float hi){
    u64 r; asm("mov.b64 %0, {%1, %2};" : "=l"(r) : "f"(lo), "f"(hi)); return r;
}
__device__ __forceinline__ void up2(u64 p, float& lo, float& hi){
    asm("mov.b64 {%0, %1}, %2;" : "=f"(lo), "=f"(hi) : "l"(p));
}
__device__ __forceinline__ u64 addx2(u64 a, u64 b){
    u64 r; asm("add.rn.f32x2 %0, %1, %2;" : "=l"(r) : "l"(a), "l"(b)); return r;
}
__device__ __forceinline__ u64 mulx2(u64 a, u64 b){
    u64 r; asm("mul.rn.f32x2 %0, %1, %2;" : "=l"(r) : "l"(a), "l"(b)); return r;
}
__device__ __forceinline__ u64 fmax2(u64 a, u64 b, u64 c){
    u64 r; asm("fma.rn.f32x2 %0, %1, %2, %3;" : "=l"(r) : "l"(a), "l"(b), "l"(c)); return r;
}
__device__ __forceinline__ float frcp(float x){
    float r; asm("rcp.approx.f32 %0, %1;" : "=f"(r) : "f"(x)); return r;
}
__device__ __forceinline__ float fex2(float x){
    float r; asm("ex2.approx.f32 %0, %1;" : "=f"(r) : "f"(x)); return r;
}
__device__ __forceinline__ u64 shfl64(u64 v, int m){
    return __shfl_xor_sync(FULLMASK, v, m);
}

// Precomputed softplus(-gamma) * (1/temp) * log2(e), shared by all batches.
__device__ float d_gp2[64 * 64];

__global__ void prep_kernel(const float* __restrict__ gamma){
    int i = blockIdx.x * blockDim.x + threadIdx.x;
    if (i < 64 * 64){
        float g = gamma[i];
        float sp = (g > 0.f) ? log1pf(expf(-g)) : (-g + log1pf(expf(g)));
        d_gp2[i] = sp * 14.4269504088896341f;   // * 10 (1/temp) * log2(e)
    }
}

// 512 threads = 16 warps = 8 matrix-pairs per CTA.
__global__ void __launch_bounds__(512, 1) sinkhorn_kernel(
        const float* __restrict__ noise, float* __restrict__ out, int B){
    // exchange buffers: [parity][pair][warp][tj][4 pieces]  (8 KB)
    __shared__ u64 xbuf[2][8][2][8][4];

    int tid  = threadIdx.x;
    int pair = tid >> 6;                 // 0..7  (matrix within CTA)
    int w    = (tid >> 5) & 1;           // warp within pair (row half)
    int lane = tid & 31;
    int tj   = lane & 7;                 // column group: cols tj*8 .. tj*8+7
    int ti2  = lane >> 3;                // row subgroup (0..3) within warp half

    int mat = blockIdx.x * 8 + pair;
    if (mat >= B) return;                // whole pair exits together

    int rbase = w * 32 + ti2 * 8;        // first of this lane's 8 rows
    int col0  = tj * 8;
    int barid = 1 + pair;                // named barrier per pair (ids 1..8)

    const float* np = noise + ((size_t)mat * 64 + rbase) * 64 + col0;
    const float* gp = d_gp2 + rbase * 64 + col0;
    const float KS = 14.4269504088896341f;   // 10 * log2(e)

    // K2[rp][j] packs rows (rbase+2rp, rbase+2rp+1) for column col0+j.
    u64 K2[4][8];

    // ---- load, scale into log2 domain, per-row max, exponentiate ----
    {
        float ma[4], mb[4];
        #pragma unroll
        for (int rp = 0; rp < 4; ++rp){
            const float* pa = np + (size_t)(2 * rp) * 64;
            const float* pb = pa + 64;
            const float* ga = gp + (2 * rp) * 64;
            const float* gb = ga + 64;
            float xa[8], xb[8];
            float4 a0 = *(const float4*)(pa);
            float4 a1 = *(const float4*)(pa + 4);
            float4 b0 = *(const float4*)(pb);
            float4 b1 = *(const float4*)(pb + 4);
            float4 g0 = *(const float4*)(ga);
            float4 g1 = *(const float4*)(ga + 4);
            float4 h0 = *(const float4*)(gb);
            float4 h1 = *(const float4*)(gb + 4);
            xa[0]=fmaf(a0.x,KS,g0.x); xa[1]=fmaf(a0.y,KS,g0.y);
            xa[2]=fmaf(a0.z,KS,g0.z); xa[3]=fmaf(a0.w,KS,g0.w);
            xa[4]=fmaf(a1.x,KS,g1.x); xa[5]=fmaf(a1.y,KS,g1.y);
            xa[6]=fmaf(a1.z,KS,g1.z); xa[7]=fmaf(a1.w,KS,g1.w);
            xb[0]=fmaf(b0.x,KS,h0.x); xb[1]=fmaf(b0.y,KS,h0.y);
            xb[2]=fmaf(b0.z,KS,h0.z); xb[3]=fmaf(b0.w,KS,h0.w);
            xb[4]=fmaf(b1.x,KS,h1.x); xb[5]=fmaf(b1.y,KS,h1.y);
            xb[6]=fmaf(b1.z,KS,h1.z); xb[7]=fmaf(b1.w,KS,h1.w);
            #pragma unroll
            for (int j = 0; j < 8; ++j) K2[rp][j] = pk2(xa[j], xb[j]);
            ma[rp] = fmaxf(fmaxf(fmaxf(xa[0],xa[1]),fmaxf(xa[2],xa[3])),
                           fmaxf(fmaxf(xa[4],xa[5]),fmaxf(xa[6],xa[7])));
            mb[rp] = fmaxf(fmaxf(fmaxf(xb[0],xb[1]),fmaxf(xb[2],xb[3])),
                           fmaxf(fmaxf(xb[4],xb[5]),fmaxf(xb[6],xb[7])));
        }
        // row max across the 8 tj lanes (rows live entirely in this warp)
        #pragma unroll
        for (int rp = 0; rp < 4; ++rp){
            float a = ma[rp], b = mb[rp];
            a = fmaxf(a, __shfl_xor_sync(FULLMASK, a, 1));
            a = fmaxf(a, __shfl_xor_sync(FULLMASK, a, 2));
            a = fmaxf(a, __shfl_xor_sync(FULLMASK, a, 4));
            b = fmaxf(b, __shfl_xor_sync(FULLMASK, b, 1));
            b = fmaxf(b, __shfl_xor_sync(FULLMASK, b, 2));
            b = fmaxf(b, __shfl_xor_sync(FULLMASK, b, 4));
            u64 nm = pk2(-a, -b);
            #pragma unroll
            for (int j = 0; j < 8; ++j){
                u64 t = addx2(K2[rp][j], nm);
                float u, v; up2(t, u, v);
                K2[rp][j] = pk2(fex2(u), fex2(v));
            }
        }
    }

    // ---- 50 iterations on scaling vectors ----
    u64 cb2[8];                     // (c_j, c_j) broadcast pairs for own 8 cols
    #pragma unroll
    for (int j = 0; j < 8; ++j) cb2[j] = pk2(1.f, 1.f);
    u64 rv2[4];                     // packed row scales for this lane's 8 rows

    #pragma unroll 1
    for (int it = 0; it < 50; ++it){
        // ---- r = 1/(K c): row-packed matvec, butterfly over tj, rcp ----
        #pragma unroll
        for (int rp = 0; rp < 4; ++rp){
            u64 acc = mulx2(K2[rp][0], cb2[0]);
            #pragma unroll
            for (int j = 1; j < 8; ++j) acc = fmax2(K2[rp][j], cb2[j], acc);
            acc = addx2(acc, shfl64(acc, 1));
            acc = addx2(acc, shfl64(acc, 2));
            acc = addx2(acc, shfl64(acc, 4));
            float u, v; up2(acc, u, v);
            rv2[rp] = pk2(frcp(u), frcp(v));
        }

        // ---- partial col sums over this warp's 32 rows ----
        float cp[8];
        #pragma unroll
        for (int j = 0; j < 8; ++j){
            u64 t = mulx2(K2[0][j], rv2[0]);
            t = fmax2(K2[1][j], rv2[1], t);
            t = fmax2(K2[2][j], rv2[2], t);
            t = fmax2(K2[3][j], rv2[3], t);
            float u, v; up2(t, u, v);
            cp[j] = u + v;
        }
        u64 P0 = pk2(cp[0], cp[1]);
        u64 P1 = pk2(cp[2], cp[3]);
        u64 P2 = pk2(cp[4], cp[5]);
        u64 P3 = pk2(cp[6], cp[7]);
        // butterfly over the 4 ti2 subgroups (lanes at stride 8)
        P0 = addx2(P0, shfl64(P0, 8));  P1 = addx2(P1, shfl64(P1, 8));
        P2 = addx2(P2, shfl64(P2, 8));  P3 = addx2(P3, shfl64(P3, 8));
        P0 = addx2(P0, shfl64(P0, 16)); P1 = addx2(P1, shfl64(P1, 16));
        P2 = addx2(P2, shfl64(P2, 16)); P3 = addx2(P3, shfl64(P3, 16));

        // ---- cross-warp exchange (per-tj slots, double buffered) ----
        int par = it & 1;
        if (ti2 == 0){
            u64* dst = &xbuf[par][pair][w][tj][0];
            dst[0] = P0; dst[1] = P1; dst[2] = P2; dst[3] = P3;
        }
        asm volatile("bar.sync %0, %1;" :: "r"(barid), "r"(64) : "memory");
        const u64* src = &xbuf[par][pair][1 - w][tj][0];
        P0 = addx2(P0, src[0]);
        P1 = addx2(P1, src[1]);
        P2 = addx2(P2, src[2]);
        P3 = addx2(P3, src[3]);

        // ---- c = 1/colsum, rebuilt as broadcast pairs ----
        float u, v;
        up2(P0, u, v); cb2[0] = pk2(frcp(u), frcp(u)); cb2[1] = pk2(frcp(v), frcp(v));
        up2(P1, u, v); cb2[2] = pk2(frcp(u), frcp(u)); cb2[3] = pk2(frcp(v), frcp(v));
        up2(P2, u, v); cb2[4] = pk2(frcp(u), frcp(u)); cb2[5] = pk2(frcp(v), frcp(v));
        up2(P3, u, v); cb2[6] = pk2(frcp(u), frcp(u)); cb2[7] = pk2(frcp(v), frcp(v));
    }

    // ---- materialize out = diag(r) K diag(c) and store ----
    float* op = out + ((size_t)mat * 64 + rbase) * 64 + col0;
    #pragma unroll
    for (int rp = 0; rp < 4; ++rp){
        float a[8], b[8];
        #pragma unroll
        for (int j = 0; j < 8; ++j){
            u64 t = mulx2(mulx2(K2[rp][j], rv2[rp]), cb2[j]);
            up2(t, a[j], b[j]);
        }
        float* ra = op + (size_t)(2 * rp) * 64;
        float* rb = ra + 64;
        *(float4*)(ra)     = make_float4(a[0], a[1], a[2], a[3]);
        *(float4*)(ra + 4) = make_float4(a[4], a[5], a[6], a[7]);
        *(float4*)(rb)     = make_float4(b[0], b[1], b[2], b[3]);
        *(float4*)(rb + 4) = make_float4(b[4], b[5], b[6], b[7]);
    }
}

extern "C" void kernel_launch(void* const* d_in, const int* in_sizes, int n_in,
                              void* d_out, int out_size) {
    const float* gamma = (const float*)d_in[0];   // [64,64] fp32
    const float* noise = (const float*)d_in[1];   // [B,64,64] fp32
    float* out = (float*)d_out;                   // [B,64,64] fp32
    int B = in_sizes[1] / (64 * 64);

    prep_kernel<<<16, 256>>>(gamma);
    int blocks = (B + 7) / 8;                     // 8 matrices (16 warps) per CTA
    sinkhorn_kernel<<<blocks, 512>>>(noise, out, B);
}